// round 14
// baseline (speedup 1.0000x reference)
#include <cuda_runtime.h>
#include <cuda_fp16.h>
#include <cstdint>

// CostVolume: cost[b,i,h,x] = (1/128) sum_c L[b,c,h,x]*R[b,c,h,x-i], 0 for x<i.
// b=8 c=128 h=96 w=320, 48 disp, fp32.
// v14: fully warp-specialized fp16 mma pipeline, 4 CTAs/SM.
//   producers (warps 4-7): ALL loads+converts (A and B) as a free-running
//     24-task stream (6/slice), rolling 3-slot reg buffer, bar.arrive FULL[kc].
//   consumers (warps 0-3): pure ldsm+mma (warp = m-tile x 8 n-tiles, C[8][4]);
//     small live set -> 64-reg target -> 4 CTAs/SM -> 16 producer warps/SM
//     of LDG in flight to saturate DRAM.

#define BB 8
#define CH 128
#define HH 96
#define WW 320
#define MAXD 48
#define PLANE (HH*WW)

#define ROWB 256         // fp16 tile row bytes: 128 k * 2B
#define AF 0             // A fp16: 64*256  = 16384
#define BF 16384         // B fp16: 112*256 = 28672
#define SMEM_TOTAL 45056

__device__ __forceinline__ uint32_t gfun(uint32_t m){
    return ((((m>>2)&1)<<2) | ((((m>>1)^(m>>4))&1)<<1) | (((m^(m>>3))&1)));
}
__device__ __forceinline__ uint32_t smem_u32(const void* p){
    uint32_t a;
    asm("{ .reg .u64 t; cvta.to.shared.u64 t, %1; cvt.u32.u64 %0, t; }" : "=r"(a) : "l"(p));
    return a;
}
__device__ __forceinline__ uint32_t cvt_f16x2(float v0, float v1){
    uint32_t r;
    asm("cvt.rn.f16x2.f32 %0, %1, %2;" : "=r"(r) : "f"(v1), "f"(v0));
    return r;
}
__device__ __forceinline__ void ldsm_x4(uint32_t* r, uint32_t addr){
    asm volatile("ldmatrix.sync.aligned.m8n8.x4.shared.b16 {%0,%1,%2,%3}, [%4];"
                 : "=r"(r[0]), "=r"(r[1]), "=r"(r[2]), "=r"(r[3]) : "r"(addr));
}
__device__ __forceinline__ void mma16816(float* c, const uint32_t* a, const uint32_t* b){
    asm volatile("mma.sync.aligned.m16n8k16.row.col.f32.f16.f16.f32 "
                 "{%0,%1,%2,%3}, {%4,%5,%6,%7}, {%8,%9}, {%0,%1,%2,%3};"
                 : "+f"(c[0]), "+f"(c[1]), "+f"(c[2]), "+f"(c[3])
                 : "r"(a[0]), "r"(a[1]), "r"(a[2]), "r"(a[3]), "r"(b[0]), "r"(b[1]));
}
__device__ __forceinline__ float4 zero4(){ return make_float4(0.f,0.f,0.f,0.f); }

#define BAR_SYNC(id, cnt)   asm volatile("bar.sync %0, %1;"   :: "r"(id), "r"(cnt) : "memory")
#define BAR_ARRIVE(id, cnt) asm volatile("bar.arrive %0, %1;" :: "r"(id), "r"(cnt) : "memory")

__global__ __launch_bounds__(256, 4)
void costvol_v14_kernel(const float* __restrict__ L,
                        const float* __restrict__ R,
                        float* __restrict__ out)
{
    extern __shared__ char smem[];
    const uint32_t sb = smem_u32(smem);

    const int tid  = threadIdx.x;
    const int warp = tid >> 5;
    const int lane = tid & 31;

    const int xt = blockIdx.x % 5;
    const int bh = blockIdx.x / 5;
    const int h  = bh % HH;
    const int b  = bh / HH;
    const int X0 = 64 * xt;

    const float* Lbh = L + ((size_t)b * CH * HH + h) * WW;
    const float* Rbh = R + ((size_t)b * CH * HH + h) * WW;

    float* Ob = (float*)smem;            // epilogue buffer overlays A tile

    if (warp < 4){
        // ===================== CONSUMER (warps 0-3): mma only =====================
        const int mt = warp;             // m-tile; n-tiles 2mt..2mt+7
        const int m0 = 16 * mt;
        const int lg = lane >> 3, l8 = lane & 7;
        const int arow = m0 + l8 + ((lg & 1) ? 8 : 0);
        const int asel = lg >> 1;
        const uint32_t gAr = gfun((uint32_t)arow);
        const int colselB = (lane >> 3) & 1;
        const int hi16 = (lane >> 4) & 1;
        int brow[4]; uint32_t gB4[4];
        #pragma unroll
        for (int j = 0; j < 4; j++){
            brow[j] = 8 * (2*mt + 2*j + hi16) + (lane & 7);
            gB4[j]  = gfun((uint32_t)brow[j]);
        }

        float C[8][4];
        #pragma unroll
        for (int t = 0; t < 8; t++)
            #pragma unroll
            for (int f = 0; f < 4; f++) C[t][f] = 0.f;

        #pragma unroll 1
        for (int kc = 0; kc < 4; kc++){
            BAR_SYNC(kc + 1, 256);       // slice kc (A and B) ready
            #pragma unroll
            for (int ktl = 0; ktl < 2; ktl++){
                uint32_t colA = (uint32_t)(kc * 4 + 2 * ktl + asel);
                uint32_t af[4];
                ldsm_x4(af, sb + AF + (uint32_t)arow * ROWB + ((colA ^ gAr) << 4));
                #pragma unroll
                for (int j = 0; j < 4; j++){
                    uint32_t colB = (uint32_t)(kc * 4 + 2 * ktl + colselB);
                    uint32_t bf[4];
                    ldsm_x4(bf, sb + BF + (uint32_t)brow[j] * ROWB + ((colB ^ gB4[j]) << 4));
                    mma16816(C[2*j],     af, bf);       // n-tile 2mt+2j
                    mma16816(C[2*j + 1], af, bf + 2);   // n-tile 2mt+2j+1
                }
            }
        }
        BAR_SYNC(5, 128);                // consumers done before Ob overlays A

        // band extract into Ob[i][m] (stride 68), scale 1/128
        const int r  = lane >> 2;
        const int cb = 2 * (lane & 3);
        const float scale = 1.0f / 128.0f;
        #pragma unroll
        for (int tn = 0; tn < 8; tn++){
            int p = 2*mt + tn;
            #pragma unroll
            for (int f = 0; f < 4; f++){
                int row  = r + ((f >= 2) ? 8 : 0);
                int col  = cb + (f & 1);
                int mloc = m0 + row;
                int n    = 8*p + col;
                int i    = mloc + 48 - n;
                if (i >= 0 && i < MAXD)
                    Ob[i * 68 + mloc] = C[tn][f] * scale;
            }
        }
    } else {
        // ================= PRODUCER (warps 4-7): all loads+converts =================
        // B lanes: kpB = 4*pw + kpq (kpq = (lane>>3)&3), n-octet n8 = lane&7.
        // A lanes: t2 = tid-128: kplA = t2>>4 (0..7), m4a = t2&15.
        // Stream: 24 tasks, 6/slice: j=0..3 B(g4=j), j=4 A(kplA), j=5 A(kplA+8).
        const int pw  = warp - 4;
        const int kpq = (lane >> 3) & 3;
        const int n8  = lane & 7;
        const int kpB = 4 * pw + kpq;
        const uint32_t w4B = (uint32_t)kpq << 2;
        const int t2   = tid - 128;
        const int kplA = t2 >> 4;
        const int m4a  = t2 & 15;
        const float* pLa = Lbh + X0 + 4 * m4a;
        const int xrB = X0 - 48 + 4 * (8 * 0 + n8);   // recomputed per task below

        float4 bu[3], bv[3];

        auto ldTask = [&](int s){
            const int kc = s / 6, j = s % 6;
            const int sl = s % 3;
            if (j < 4){
                int n4 = 8 * j + n8;
                int xr = X0 - 48 + 4 * n4;
                bool v = (n4 < 28) && (xr >= 0);
                const float* p = Rbh + (size_t)(2 * (kc * 16 + kpB)) * PLANE + (v ? xr : 0);
                bu[sl] = v ? *(const float4*)p           : zero4();
                bv[sl] = v ? *(const float4*)(p + PLANE) : zero4();
            } else {
                int kpa = kplA + ((j == 5) ? 8 : 0);
                const float* p = pLa + (size_t)(2 * (kc * 16 + kpa)) * PLANE;
                bu[sl] = *(const float4*)p;
                bv[sl] = *(const float4*)(p + PLANE);
            }
        };

        auto cvTask = [&](int s){
            const int kc = s / 6, j = s % 6;
            const int sl = s % 3;
            const float va[4] = {bu[sl].x, bu[sl].y, bu[sl].z, bu[sl].w};
            const float vb[4] = {bv[sl].x, bv[sl].y, bv[sl].z, bv[sl].w};
            if (j < 4){
                int n4 = 8 * j + n8;
                if (n4 < 28){
                    uint32_t c16 = (uint32_t)(4 * kc + pw);
                    #pragma unroll
                    for (int e = 0; e < 4; e++){
                        uint32_t n = (uint32_t)(4*n4 + e);
                        uint32_t off = n * ROWB + ((c16 ^ gfun(n)) << 4) + w4B;
                        *(uint32_t*)(smem + BF + off) = cvt_f16x2(va[e], vb[e]);
                    }
                }
            } else {
                int kpa = kplA + ((j == 5) ? 8 : 0);
                uint32_t kpg = (uint32_t)(kc * 16 + kpa);
                uint32_t c16 = kpg >> 2, w4 = (kpg & 3) << 2;
                #pragma unroll
                for (int e = 0; e < 4; e++){
                    uint32_t m = (uint32_t)(4*m4a + e);
                    uint32_t off = m * ROWB + ((c16 ^ gfun(m)) << 4) + w4;
                    *(uint32_t*)(smem + AF + off) = cvt_f16x2(va[e], vb[e]);
                }
            }
        };

        ldTask(0); ldTask(1);
        #pragma unroll
        for (int s = 0; s < 24; s++){
            if (s + 2 < 24) ldTask(s + 2);
            cvTask(s);
            if (s % 6 == 5) BAR_ARRIVE(s / 6 + 1, 256);   // slice ready
        }
        (void)xrB;
    }

    __syncthreads();                     // Ob complete, all joined

    // coalesced store: 48 rows x 64 floats
    float* ob = out + (((size_t)b * MAXD) * HH + h) * WW + X0;
    #pragma unroll
    for (int q = tid; q < MAXD * 16; q += 256){
        int i = q >> 4, c4 = q & 15;
        float4 v = *(const float4*)(Ob + i * 68 + 4 * c4);
        *(float4*)(ob + (size_t)i * PLANE + 4 * c4) = v;
    }
}

extern "C" void kernel_launch(void* const* d_in, const int* in_sizes, int n_in,
                              void* d_out, int out_size)
{
    const float* L = (const float*)d_in[0];
    const float* R = (const float*)d_in[1];
    float* out = (float*)d_out;

    cudaFuncSetAttribute(costvol_v14_kernel,
                         cudaFuncAttributeMaxDynamicSharedMemorySize, SMEM_TOTAL);
    dim3 grid(BB * HH * 5);   // 3840 CTAs: (b, h, x-tile of 64)
    costvol_v14_kernel<<<grid, 256, SMEM_TOTAL>>>(L, R, out);
}

// round 15
// speedup vs baseline: 1.0975x; 1.0975x over previous
#include <cuda_runtime.h>
#include <cuda_fp16.h>
#include <cstdint>

// CostVolume: cost[b,i,h,x] = (1/128) sum_c L[b,c,h,x]*R[b,c,h,x-i], 0 for x<i.
// b=8 c=128 h=96 w=320, 48 disp, fp32.
// v15 = persistent v8: the proven inner loop (fp16 mma.sync.m16n8k16, fp32 accum,
// K in 4 slices of 32, register prefetch, 1 barrier/slice) run by 444 persistent
// CTAs with a dynamic ticket. Cross-unit prefetch: at kc==3 the prefetch slot
// loads the NEXT unit's slice 0 (ticket pre-drawn at kc==1, published via the
// existing kc-barriers). Dedicated epilogue buffer (no A-tile overlay) drops one
// barrier per unit and lets stores overlap the next unit's converts.

#define BB 8
#define CH 128
#define HH 96
#define WW 320
#define MAXD 48
#define PLANE (HH*WW)
#define NUNITS (BB*HH*5)   // 3840

#define ROWB 256           // fp16 tile row bytes: 128 k * 2B
#define AF 0               // A fp16: 64*256  = 16384
#define BF 16384           // B fp16: 112*256 = 28672
#define OBOFF 45056        // epilogue buffer: 48*68*4 = 13056
#define SMEM_TOTAL 58112

__device__ int g_ticket;

__device__ __forceinline__ uint32_t gfun(uint32_t m){
    return ((((m>>2)&1)<<2) | ((((m>>1)^(m>>4))&1)<<1) | (((m^(m>>3))&1)));
}
__device__ __forceinline__ uint32_t smem_u32(const void* p){
    uint32_t a;
    asm("{ .reg .u64 t; cvta.to.shared.u64 t, %1; cvt.u32.u64 %0, t; }" : "=r"(a) : "l"(p));
    return a;
}
__device__ __forceinline__ uint32_t cvt_f16x2(float v0, float v1){
    uint32_t r;
    asm("cvt.rn.f16x2.f32 %0, %1, %2;" : "=r"(r) : "f"(v1), "f"(v0));
    return r;
}
__device__ __forceinline__ void ldsm_x4(uint32_t* r, uint32_t addr){
    asm volatile("ldmatrix.sync.aligned.m8n8.x4.shared.b16 {%0,%1,%2,%3}, [%4];"
                 : "=r"(r[0]), "=r"(r[1]), "=r"(r[2]), "=r"(r[3]) : "r"(addr));
}
__device__ __forceinline__ void mma16816(float* c, const uint32_t* a, const uint32_t* b){
    asm volatile("mma.sync.aligned.m16n8k16.row.col.f32.f16.f16.f32 "
                 "{%0,%1,%2,%3}, {%4,%5,%6,%7}, {%8,%9}, {%0,%1,%2,%3};"
                 : "+f"(c[0]), "+f"(c[1]), "+f"(c[2]), "+f"(c[3])
                 : "r"(a[0]), "r"(a[1]), "r"(a[2]), "r"(a[3]), "r"(b[0]), "r"(b[1]));
}
__device__ __forceinline__ float4 zero4(){ return make_float4(0.f,0.f,0.f,0.f); }

__global__ __launch_bounds__(256, 3)
void costvol_v15_kernel(const float* __restrict__ L,
                        const float* __restrict__ R,
                        float* __restrict__ out)
{
    extern __shared__ char smem[];
    const uint32_t sb = smem_u32(smem);
    __shared__ int s_next;

    const int tid  = threadIdx.x;
    const int warp = tid >> 5;
    const int lane = tid & 31;

    // ---- thread maps (unit-independent), identical to v8 ----
    const int kplA = tid >> 4;            // 0..15
    const int m4a  = tid & 15;
    uint32_t gA[4];
    #pragma unroll
    for (int e = 0; e < 4; e++) gA[e] = gfun((uint32_t)(4*m4a + e));

    const int kplB0 = tid / 28, n4b0 = tid - 28 * kplB0;
    const int tB1 = tid + 256;
    const bool act1 = (tB1 < 448);
    const int kplB1 = act1 ? tB1 / 28 : 0;
    const int n4b1  = act1 ? (tB1 - 28 * kplB1) : 0;
    uint32_t gB0[4], gB1[4];
    #pragma unroll
    for (int e = 0; e < 4; e++){
        gB0[e] = gfun((uint32_t)(4*n4b0 + e));
        gB1[e] = gfun((uint32_t)(4*n4b1 + e));
    }

    // ---- mma lane constants (identical to v8) ----
    const int mt = warp >> 1, nh = warp & 1;
    const int m0 = 16 * mt;
    const int lg = lane >> 3, l8 = lane & 7;
    const int arow = m0 + l8 + ((lg & 1) ? 8 : 0);
    const int asel = lg >> 1;
    const uint32_t gArow = gfun((uint32_t)arow);
    const int colselB = (lane >> 3) & 1;
    int browv[4]; uint32_t gBrow[4];
    #pragma unroll
    for (int j = 0; j < 2; j++){
        int p = 2*mt + 4*nh + 2*j + ((lane >> 4) & 1);
        browv[j] = 8*p + (lane & 7);
        gBrow[j] = gfun((uint32_t)browv[j]);
    }

    float C[4][4];
    float4 a0, a1, b00, b01, b10, b11;

    // ---- unit addressing + prefetch (v8 body, parametrized by unit ptrs) ----
    auto unit_LR = [&](int uu, const float*& Lb_, const float*& Rb_, int& X0_){
        int xt = uu % 5, bhv = uu / 5;
        int h = bhv % HH, b = bhv / HH;
        X0_ = 64 * xt;
        Lb_ = L + ((size_t)b * CH * HH + h) * WW;
        Rb_ = R + ((size_t)b * CH * HH + h) * WW;
    };
    auto prefetch = [&](const float* Lb_, const float* Rb_, int X0_, int kc){
        const float* pLa = Lb_ + X0_ + 4 * m4a;
        int c0a = 2 * (kc * 16 + kplA);
        a0 = *(const float4*)(pLa + (size_t)c0a * PLANE);
        a1 = *(const float4*)(pLa + (size_t)(c0a + 1) * PLANE);
        int xr0 = X0_ - 48 + 4 * n4b0;
        int c0b = 2 * (kc * 16 + kplB0);
        if (xr0 >= 0){
            b00 = *(const float4*)(Rb_ + (size_t)c0b * PLANE + xr0);
            b01 = *(const float4*)(Rb_ + (size_t)(c0b + 1) * PLANE + xr0);
        } else { b00 = zero4(); b01 = zero4(); }
        int xr1 = X0_ - 48 + 4 * n4b1;
        int c1b = 2 * (kc * 16 + kplB1);
        if (act1 && xr1 >= 0){
            b10 = *(const float4*)(Rb_ + (size_t)c1b * PLANE + xr1);
            b11 = *(const float4*)(Rb_ + (size_t)(c1b + 1) * PLANE + xr1);
        } else { b10 = zero4(); b11 = zero4(); }
    };
    auto convert_sts = [&](int kc){
        {   // A slice
            uint32_t kpg = (uint32_t)(kc * 16 + kplA);
            uint32_t c16 = kpg >> 2, w4 = (kpg & 3) << 2;
            const float va[4] = {a0.x, a0.y, a0.z, a0.w};
            const float vb[4] = {a1.x, a1.y, a1.z, a1.w};
            #pragma unroll
            for (int e = 0; e < 4; e++){
                uint32_t m = (uint32_t)(4*m4a + e);
                uint32_t off = m * ROWB + ((c16 ^ gA[e]) << 4) + w4;
                *(uint32_t*)(smem + AF + off) = cvt_f16x2(va[e], vb[e]);
            }
        }
        {   // B task 0
            uint32_t kpg = (uint32_t)(kc * 16 + kplB0);
            uint32_t c16 = kpg >> 2, w4 = (kpg & 3) << 2;
            const float va[4] = {b00.x, b00.y, b00.z, b00.w};
            const float vb[4] = {b01.x, b01.y, b01.z, b01.w};
            #pragma unroll
            for (int e = 0; e < 4; e++){
                uint32_t n = (uint32_t)(4*n4b0 + e);
                uint32_t off = n * ROWB + ((c16 ^ gB0[e]) << 4) + w4;
                *(uint32_t*)(smem + BF + off) = cvt_f16x2(va[e], vb[e]);
            }
        }
        if (act1){  // B task 1
            uint32_t kpg = (uint32_t)(kc * 16 + kplB1);
            uint32_t c16 = kpg >> 2, w4 = (kpg & 3) << 2;
            const float va[4] = {b10.x, b10.y, b10.z, b10.w};
            const float vb[4] = {b11.x, b11.y, b11.z, b11.w};
            #pragma unroll
            for (int e = 0; e < 4; e++){
                uint32_t n = (uint32_t)(4*n4b1 + e);
                uint32_t off = n * ROWB + ((c16 ^ gB1[e]) << 4) + w4;
                *(uint32_t*)(smem + BF + off) = cvt_f16x2(va[e], vb[e]);
            }
        }
    };

    // ---- persistent loop ----
    if (tid == 0) s_next = atomicAdd(&g_ticket, 1);
    __syncthreads();
    int u = s_next;
    if (u >= NUNITS) return;             // uniform across CTA

    const float* Lc; const float* Rc; int X0c;
    unit_LR(u, Lc, Rc, X0c);
    prefetch(Lc, Rc, X0c, 0);

    float* Ob = (float*)(smem + OBOFF);

    int u2 = u;
    while (u < NUNITS){
        #pragma unroll
        for (int t = 0; t < 4; t++)
            #pragma unroll
            for (int f = 0; f < 4; f++) C[t][f] = 0.f;

        #pragma unroll 1
        for (int kc = 0; kc < 4; kc++){
            convert_sts(kc);
            if (kc == 1 && tid == 0) s_next = atomicAdd(&g_ticket, 1);
            if (kc < 3){
                prefetch(Lc, Rc, X0c, kc + 1);
            } else {
                u2 = s_next;             // published through kc=1..2 barriers
                int uc = (u2 < NUNITS) ? u2 : 0;
                const float* Ln; const float* Rn; int X0n;
                unit_LR(uc, Ln, Rn, X0n);
                prefetch(Ln, Rn, X0n, 0);   // next unit's slice 0
            }
            __syncthreads();             // slice kc visible to all warps

            #pragma unroll
            for (int ktl = 0; ktl < 2; ktl++){
                uint32_t colA = (uint32_t)(kc * 4 + 2 * ktl + asel);
                uint32_t af[4];
                ldsm_x4(af, sb + AF + (uint32_t)arow * ROWB + ((colA ^ gArow) << 4));
                #pragma unroll
                for (int j = 0; j < 2; j++){
                    uint32_t colB = (uint32_t)(kc * 4 + 2 * ktl + colselB);
                    uint32_t bf[4];
                    ldsm_x4(bf, sb + BF + (uint32_t)browv[j] * ROWB + ((colB ^ gBrow[j]) << 4));
                    mma16816(C[2*j],     af, bf);       // tn = 2j
                    mma16816(C[2*j + 1], af, bf + 2);   // tn = 2j+1
                }
            }
        }

        // ---- band extract into dedicated Ob[i][m] (stride 68), scale 1/128 ----
        {
            const int r  = lane >> 2;
            const int cb = 2 * (lane & 3);
            const float scale = 1.0f / 128.0f;
            #pragma unroll
            for (int tn = 0; tn < 4; tn++){
                int p = 2*mt + 4*nh + tn;
                #pragma unroll
                for (int f = 0; f < 4; f++){
                    int row  = r + ((f >= 2) ? 8 : 0);
                    int col  = cb + (f & 1);
                    int mloc = m0 + row;
                    int n    = 8*p + col;
                    int i    = mloc + 48 - n;
                    if (i >= 0 && i < MAXD)
                        Ob[i * 68 + mloc] = C[tn][f] * scale;
                }
            }
        }
        __syncthreads();                 // Ob complete before store

        // ---- coalesced store for unit u ----
        {
            int xt = u % 5, bhv = u / 5;
            int h = bhv % HH, b = bhv / HH;
            float* ob = out + (((size_t)b * MAXD) * HH + h) * WW + 64 * xt;
            #pragma unroll
            for (int q = tid; q < MAXD * 16; q += 256){
                int i = q >> 4, c4 = q & 15;
                float4 v = *(const float4*)(Ob + i * 68 + 4 * c4);
                *(float4*)(ob + (size_t)i * PLANE + 4 * c4) = v;
            }
        }

        u = u2;
        unit_LR((u < NUNITS) ? u : 0, Lc, Rc, X0c);
        // prefetch regs already hold (u, slice 0); next iteration converts them.
    }
}

extern "C" void kernel_launch(void* const* d_in, const int* in_sizes, int n_in,
                              void* d_out, int out_size)
{
    const float* L = (const float*)d_in[0];
    const float* R = (const float*)d_in[1];
    float* out = (float*)d_out;

    void* taddr = nullptr;
    cudaGetSymbolAddress(&taddr, g_ticket);
    cudaMemsetAsync(taddr, 0, sizeof(int));   // graph-capturable memset node

    cudaFuncSetAttribute(costvol_v15_kernel,
                         cudaFuncAttributeMaxDynamicSharedMemorySize, SMEM_TOTAL);
    dim3 grid(444);   // 148 SMs x 3 CTAs, persistent with dynamic tickets
    costvol_v15_kernel<<<grid, 256, SMEM_TOTAL>>>(L, R, out);
}